// round 13
// baseline (speedup 1.0000x reference)
#include <cuda_runtime.h>
#include <cuda_bf16.h>

// Problem constants
#define Bb 64
#define Nn 197
#define Dd 768
#define Hh 12
#define HDd 64
#define MROWS (Bb * Nn)          // 12608
#define NTAB 30
#define SCALE 0.125f

// ---------------------------------------------------------------------------
// Scratch (device globals)
// ---------------------------------------------------------------------------
__device__ float g_q[Bb * Hh * Nn * HDd];
__device__ float g_k[Bb * Hh * Nn * HDd];
__device__ float g_v[Bb * Hh * Nn * HDd];
__device__ float g_o[MROWS * Dd];

__device__ __nv_bfloat16 g_xh[MROWS * Dd];   // x split hi/lo
__device__ __nv_bfloat16 g_xl[MROWS * Dd];
__device__ __nv_bfloat16 g_oh[MROWS * Dd];   // attention-out split hi/lo
__device__ __nv_bfloat16 g_ol[MROWS * Dd];
__device__ __nv_bfloat16 g_wth[4][Dd * Dd];  // W^T hi/lo, [n][k] K-major
__device__ __nv_bfloat16 g_wtl[4][Dd * Dd];

// ---------------------------------------------------------------------------
// Warp-level MMA helpers (baseline PTX, sm_80+: valid for plain sm_103)
// ---------------------------------------------------------------------------
__device__ __forceinline__ unsigned smem_u32(const void* p) {
    unsigned a;
    asm("{ .reg .u64 t; cvta.to.shared.u64 t, %1; cvt.u32.u64 %0, t; }" : "=r"(a) : "l"(p));
    return a;
}
__device__ __forceinline__ void ldsm4(unsigned* r, unsigned addr) {
    asm volatile("ldmatrix.sync.aligned.m8n8.x4.shared.b16 {%0,%1,%2,%3}, [%4];"
                 : "=r"(r[0]), "=r"(r[1]), "=r"(r[2]), "=r"(r[3]) : "r"(addr));
}
__device__ __forceinline__ void ldsm2(unsigned* r, unsigned addr) {
    asm volatile("ldmatrix.sync.aligned.m8n8.x2.shared.b16 {%0,%1}, [%2];"
                 : "=r"(r[0]), "=r"(r[1]) : "r"(addr));
}
__device__ __forceinline__ void mma16816(float* d, const unsigned* a, const unsigned* b) {
    asm volatile(
        "mma.sync.aligned.m16n8k16.row.col.f32.bf16.bf16.f32 "
        "{%0,%1,%2,%3}, {%4,%5,%6,%7}, {%8,%9}, {%0,%1,%2,%3};"
        : "+f"(d[0]), "+f"(d[1]), "+f"(d[2]), "+f"(d[3])
        : "r"(a[0]), "r"(a[1]), "r"(a[2]), "r"(a[3]), "r"(b[0]), "r"(b[1]));
}

// ---------------------------------------------------------------------------
// Split fp32 -> (hi, lo) bf16.
// ---------------------------------------------------------------------------
__global__ __launch_bounds__(256) void split_kernel(const float* __restrict__ src_in,
                                                    int dst_is_o, int n) {
    int i = blockIdx.x * 256 + threadIdx.x;
    if (i >= n) return;
    const float* src = dst_is_o ? g_o : src_in;
    __nv_bfloat16* ph = dst_is_o ? g_oh : g_xh;
    __nv_bfloat16* pl = dst_is_o ? g_ol : g_xl;
    float v = src[i];
    __nv_bfloat16 h = __float2bfloat16(v);
    ph[i] = h;
    pl[i] = __float2bfloat16(v - __bfloat162float(h));
}

// ---------------------------------------------------------------------------
// Transpose + split weights: W[k][n] f32 -> Wt_hi/lo[n][k] bf16 (slot 0..3)
// ---------------------------------------------------------------------------
__global__ __launch_bounds__(256) void tsplit_kernel(const float* __restrict__ W, int slot) {
    __shared__ float t[32][33];
    int n0 = blockIdx.x * 32, k0 = blockIdx.y * 32;
    int tx = threadIdx.x, ty = threadIdx.y;   // (32, 8)
    #pragma unroll
    for (int r = 0; r < 4; r++)
        t[ty + 8 * r][tx] = W[(size_t)(k0 + ty + 8 * r) * Dd + n0 + tx];
    __syncthreads();
    __nv_bfloat16* th = g_wth[slot];
    __nv_bfloat16* tl = g_wtl[slot];
    #pragma unroll
    for (int r = 0; r < 4; r++) {
        float v = t[tx][ty + 8 * r];
        __nv_bfloat16 h = __float2bfloat16(v);
        size_t o = (size_t)(n0 + ty + 8 * r) * Dd + k0 + tx;
        th[o] = h;
        tl[o] = __float2bfloat16(v - __bfloat162float(h));
    }
}

// ---------------------------------------------------------------------------
// mma.sync GEMM (unchanged from R12 — passing, near HMMA-fallback ceiling)
// ---------------------------------------------------------------------------
#define KCB 32
#define NCH (Dd / KCB)            // 24
#define RSTRIDE 80
#define TILE_SB (128 * RSTRIDE)
#define BUF_SB (4 * TILE_SB)
#define GEMM_SMEM (2 * BUF_SB)    // 81920 B

__global__ __launch_bounds__(256) void tc_gemm(const float* __restrict__ bias,
                                               float* __restrict__ out,
                                               int M, int mode, int wslot, int asrc) {
    extern __shared__ char smem[];
    const unsigned sb = smem_u32(smem);
    const int tid = threadIdx.x, warp = tid >> 5, lane = tid & 31;
    const int wm = warp >> 2, wn = warp & 3;
    const int m0 = blockIdx.y * 128, n0 = blockIdx.x * 128;

    const __nv_bfloat16* Ah = asrc ? g_oh : g_xh;
    const __nv_bfloat16* Al = asrc ? g_ol : g_xl;
    const __nv_bfloat16* Bh = g_wth[wslot];
    const __nv_bfloat16* Bl = g_wtl[wslot];

    float acc[4][4][4];
    #pragma unroll
    for (int a = 0; a < 4; a++)
        #pragma unroll
        for (int b = 0; b < 4; b++)
            #pragma unroll
            for (int c = 0; c < 4; c++) acc[a][b][c] = 0.f;

    {
        #pragma unroll
        for (int it = 0; it < 8; it++) {
            int idx = tid + it * 256;
            int tile = idx >> 9, r = (idx >> 2) & 127, g = idx & 3;
            uint4 v = make_uint4(0, 0, 0, 0);
            if (tile == 0)      { if (m0 + r < M) v = ((const uint4*)(Ah + (size_t)(m0 + r) * Dd))[g]; }
            else if (tile == 1) { if (m0 + r < M) v = ((const uint4*)(Al + (size_t)(m0 + r) * Dd))[g]; }
            else if (tile == 2) v = ((const uint4*)(Bh + (size_t)(n0 + r) * Dd))[g];
            else                v = ((const uint4*)(Bl + (size_t)(n0 + r) * Dd))[g];
            *(uint4*)(smem + tile * TILE_SB + r * RSTRIDE + g * 16) = v;
        }
    }
    __syncthreads();

    for (int c = 0; c < NCH; c++) {
        const int cur = c & 1;
        const unsigned bb = sb + cur * BUF_SB;
        const bool more = (c + 1 < NCH);
        uint4 pf[8];
        if (more) {
            const int kc = (c + 1) * KCB;
            #pragma unroll
            for (int it = 0; it < 8; it++) {
                int idx = tid + it * 256;
                int tile = idx >> 9, r = (idx >> 2) & 127, g = idx & 3;
                uint4 v = make_uint4(0, 0, 0, 0);
                if (tile == 0)      { if (m0 + r < M) v = ((const uint4*)(Ah + (size_t)(m0 + r) * Dd + kc))[g]; }
                else if (tile == 1) { if (m0 + r < M) v = ((const uint4*)(Al + (size_t)(m0 + r) * Dd + kc))[g]; }
                else if (tile == 2) v = ((const uint4*)(Bh + (size_t)(n0 + r) * Dd + kc))[g];
                else                v = ((const uint4*)(Bl + (size_t)(n0 + r) * Dd + kc))[g];
                pf[it] = v;
            }
        }

        #pragma unroll
        for (int kb = 0; kb < 2; kb++) {
            unsigned ah[4][4], al[4][4];
            const int arow = (lane & 7) + ((lane >> 3) & 1) * 8;
            const unsigned acb = ((lane >> 4) & 1) * 16 + kb * 32;
            #pragma unroll
            for (int mt = 0; mt < 4; mt++) {
                unsigned aaddr = bb + (unsigned)((wm * 64 + mt * 16 + arow) * RSTRIDE) + acb;
                ldsm4(ah[mt], aaddr);
                ldsm4(al[mt], aaddr + TILE_SB);
            }
            const int nrow = wn * 32 + (lane & 7);
            const unsigned bcb = ((lane >> 3) & 1) * 16 + kb * 32;
            #pragma unroll
            for (int nt = 0; nt < 4; nt++) {
                unsigned baddr = bb + 2 * TILE_SB + (unsigned)((nrow + nt * 8) * RSTRIDE) + bcb;
                unsigned bh[2], bl[2];
                ldsm2(bh, baddr);
                ldsm2(bl, baddr + TILE_SB);
                #pragma unroll
                for (int mt = 0; mt < 4; mt++) {
                    mma16816(acc[mt][nt], ah[mt], bh);
                    mma16816(acc[mt][nt], ah[mt], bl);
                    mma16816(acc[mt][nt], al[mt], bh);
                }
            }
        }

        if (more) {
            char* nbuf = smem + (cur ^ 1) * BUF_SB;
            __syncthreads();
            #pragma unroll
            for (int it = 0; it < 8; it++) {
                int idx = tid + it * 256;
                int tile = idx >> 9, r = (idx >> 2) & 127, g = idx & 3;
                *(uint4*)(nbuf + tile * TILE_SB + r * RSTRIDE + g * 16) = pf[it];
            }
            __syncthreads();
        }
    }

    const int lr = lane >> 2, lc = (lane & 3) * 2;
    #pragma unroll
    for (int mt = 0; mt < 4; mt++) {
        #pragma unroll
        for (int nt = 0; nt < 4; nt++) {
            const int cgl = n0 + wn * 32 + nt * 8 + lc;
            const float b0 = bias[cgl], b1 = bias[cgl + 1];
            #pragma unroll
            for (int hrow = 0; hrow < 2; hrow++) {
                const int r = m0 + wm * 64 + mt * 16 + lr + hrow * 8;
                if (r >= M) continue;
                float2 o2;
                o2.x = acc[mt][nt][hrow * 2 + 0] + b0;
                o2.y = acc[mt][nt][hrow * 2 + 1] + b1;
                if (mode == 0) {
                    *(float2*)(out + (size_t)r * Dd + cgl) = o2;
                } else {
                    float* dst = (mode == 1) ? g_q : (mode == 2) ? g_k : g_v;
                    const int bidx = r / Nn, tok = r % Nn;
                    const int h = cgl >> 6, d = cgl & 63;
                    *(float2*)(dst + (((size_t)bidx * Hh + h) * Nn + tok) * HDd + d) = o2;
                }
            }
        }
    }
}

// ---------------------------------------------------------------------------
// Attention kernel: one CTA per (b,h), 12 warps, FOUR queries per warp-iter.
// K/V/table smem rows reused across 4 queries; probabilities transposed
// pt[j][4] so one broadcast LDS.128 serves all 4 queries in the V loop.
// ---------------------------------------------------------------------------
#define NW 12
#define NTH (32 * NW)             // 384
#define KVS 68
#define NGRP 50                   // ceil(197/4)
#define PTW 788                   // 197*4 floats per warp
#define ATTN_SMEM_FLOATS (2 * Nn * KVS + 4 * NTAB * KVS + NW * 256 + NW * PTW + 4 * NW * 120)

__global__ __launch_bounds__(NTH) void attn_kernel(
    const float* __restrict__ rkv, const float* __restrict__ rkh,
    const float* __restrict__ rvv, const float* __restrict__ rvh)
{
    extern __shared__ float smf[];
    float* Ks    = smf;                       // 197*68
    float* Vs    = Ks + Nn * KVS;             // 197*68
    float* rkv_s = Vs + Nn * KVS;             // 30*68 each
    float* rkh_s = rkv_s + NTAB * KVS;
    float* rvv_s = rkh_s + NTAB * KVS;
    float* rvh_s = rvv_s + NTAB * KVS;
    float* qs    = rvh_s + NTAB * KVS;        // NW*256
    float* pt    = qs + NW * 256;             // NW*788
    float* qv_s  = pt + NW * PTW;             // NW*120 x4
    float* qh_s  = qv_s + NW * 120;
    float* sv_s  = qh_s + NW * 120;
    float* sh_s  = sv_s + NW * 120;

    const int bh   = blockIdx.x;
    const int tid  = threadIdx.x;
    const int warp = tid >> 5, lane = tid & 31;
    const size_t base = (size_t)bh * Nn * HDd;
    const int b = bh / Hh, h = bh % Hh;

    // Stage K, V, tables
    for (int idx = tid; idx < Nn * HDd; idx += NTH) {
        int j = idx >> 6, d = idx & 63;
        Ks[j * KVS + d] = g_k[base + idx];
        Vs[j * KVS + d] = g_v[base + idx];
    }
    for (int idx = tid; idx < NTAB * HDd; idx += NTH) {
        int t = idx >> 6, d = idx & 63;
        rkv_s[t * KVS + d] = rkv[idx];
        rkh_s[t * KVS + d] = rkh[idx];
        rvv_s[t * KVS + d] = rvv[idx];
        rvh_s[t * KVS + d] = rvh[idx];
    }
    __syncthreads();

    float* qw  = qs + warp * 256;
    float* ptw = pt + warp * PTW;
    float* qvw = qv_s + warp * 120;
    float* qhw = qh_s + warp * 120;
    float* svw = sv_s + warp * 120;
    float* shw = sh_s + warp * 120;

    const int half = lane >> 4;        // V/table split-warp
    const int dl   = (lane & 15) * 4;

    for (int grp = warp; grp < NGRP; grp += NW) {
        const int i0 = grp * 4;
        const int nq = (i0 + 4 <= Nn) ? 4 : (Nn - i0);

        // stage 4 queries into per-warp smem (zero-fill beyond nq)
        for (int u = lane; u < 256; u += 32) {
            int q = u >> 6, d = u & 63;
            qw[u] = (q < nq) ? g_q[base + (size_t)(i0 + q) * HDd + d] : 0.f;
        }
        __syncwarp();

        // per-query table projections: qv[t][q] = q_q . rel_k_v[t]
        if (lane < NTAB) {
            const float4* tv4 = (const float4*)(rkv_s + lane * KVS);
            const float4* th4 = (const float4*)(rkh_s + lane * KVS);
            const float4* qf4 = (const float4*)qw;
            float av[4] = {0.f, 0.f, 0.f, 0.f};
            float ah[4] = {0.f, 0.f, 0.f, 0.f};
            #pragma unroll
            for (int d4 = 0; d4 < 16; d4++) {
                float4 tv = tv4[d4], th = th4[d4];
                #pragma unroll
                for (int q = 0; q < 4; q++) {
                    float4 q4 = qf4[q * 16 + d4];
                    av[q] += q4.x * tv.x + q4.y * tv.y + q4.z * tv.z + q4.w * tv.w;
                    ah[q] += q4.x * th.x + q4.y * th.y + q4.z * th.z + q4.w * th.w;
                }
            }
            #pragma unroll
            for (int q = 0; q < 4; q++) { qvw[lane * 4 + q] = av[q]; qhw[lane * 4 + q] = ah[q]; }
        }
        __syncwarp();

        int iv[4], ih[4];
        #pragma unroll
        for (int q = 0; q < 4; q++) {
            int i = i0 + q;
            iv[q] = (i == 0) ? 0 : (i - 1) / 14;
            ih[q] = (i == 0) ? 0 : (i - 1) % 14;
        }

        // scores: lane-parallel over j, 4 queries share each K row
        float s[4][7];
        float mx[4] = {-1e30f, -1e30f, -1e30f, -1e30f};
        #pragma unroll
        for (int jj = 0; jj < 7; jj++) {
            int j = lane + jj * 32;
            if (j < Nn) {
                const float4* k4 = (const float4*)(Ks + j * KVS);
                const float4* qf4 = (const float4*)qw;
                float a[4] = {0.f, 0.f, 0.f, 0.f};
                #pragma unroll
                for (int d4 = 0; d4 < 16; d4++) {
                    float4 kk = k4[d4];
                    #pragma unroll
                    for (int q = 0; q < 4; q++) {
                        float4 q4 = qf4[q * 16 + d4];   // broadcast
                        a[q] += q4.x * kk.x + q4.y * kk.y + q4.z * kk.z + q4.w * kk.w;
                    }
                }
                int rjd = (j == 0) ? 0 : (j - 1) / 14;
                int rjm = (j == 0) ? 0 : (j - 1) % 14;
                #pragma unroll
                for (int q = 0; q < 4; q++) {
                    int tv, th;
                    if (j == 0 || (i0 + q) == 0) { tv = 0; th = 0; }
                    else { tv = rjd - iv[q] + 15; th = rjm - ih[q] + 15; }
                    a[q] += qvw[tv * 4 + q] + qhw[th * 4 + q];
                    s[q][jj] = a[q] * SCALE;
                    mx[q] = fmaxf(mx[q], s[q][jj]);
                }
            } else {
                #pragma unroll
                for (int q = 0; q < 4; q++) s[q][jj] = -1e30f;
            }
        }
        #pragma unroll
        for (int q = 0; q < 4; q++)
            #pragma unroll
            for (int o = 16; o >= 1; o >>= 1) mx[q] = fmaxf(mx[q], __shfl_xor_sync(0xffffffffu, mx[q], o));

        float sum[4] = {0.f, 0.f, 0.f, 0.f};
        #pragma unroll
        for (int jj = 0; jj < 7; jj++) {
            int j = lane + jj * 32;
            if (j < Nn) {
                #pragma unroll
                for (int q = 0; q < 4; q++) { s[q][jj] = __expf(s[q][jj] - mx[q]); sum[q] += s[q][jj]; }
            }
        }
        #pragma unroll
        for (int q = 0; q < 4; q++)
            #pragma unroll
            for (int o = 16; o >= 1; o >>= 1) sum[q] += __shfl_xor_sync(0xffffffffu, sum[q], o);
        float inv[4];
        #pragma unroll
        for (int q = 0; q < 4; q++) inv[q] = 1.0f / sum[q];

        // store transposed probabilities pt[j][4]
        #pragma unroll
        for (int jj = 0; jj < 7; jj++) {
            int j = lane + jj * 32;
            if (j < Nn) {
                #pragma unroll
                for (int q = 0; q < 4; q++) ptw[j * 4 + q] = s[q][jj] * inv[q];
            }
        }
        __syncwarp();

        // bin sums per query -> sv/sh transposed [t][4]
        if (lane < NTAB) {
            #pragma unroll
            for (int q = 0; q < 4; q++) {
                float sv = 0.f, sh = 0.f;
                if (i0 == 0 && q == 0) {
                    if (lane == 0) { sv = 1.0f; sh = 1.0f; }   // softmax row sums to 1
                } else {
                    int g = lane - 15 + iv[q];
                    if (g >= 0 && g < 14) {
                        int j0 = 14 * g + 1;
                        #pragma unroll
                        for (int u = 0; u < 14; u++) sv += ptw[(j0 + u) * 4 + q];
                    }
                    int m = lane - 15 + ih[q];
                    if (m >= 0 && m < 14) {
                        #pragma unroll
                        for (int u = 0; u < 14; u++) sh += ptw[(1 + m + 14 * u) * 4 + q];
                    }
                    if (lane == 0) { sv += ptw[q]; sh += ptw[q]; }   // j=0 -> bin 0
                }
                svw[lane * 4 + q] = sv;
                shw[lane * 4 + q] = sh;
            }
        }
        __syncwarp();

        // output: split warp over j; each half-lane owns a float4 of d.
        // One V-row read + one p4 broadcast serve all 4 queries.
        float4 o0 = make_float4(0.f, 0.f, 0.f, 0.f);
        float4 o1 = o0, o2 = o0, o3 = o0;
        {
            const int jA = half ? 99 : 0;
            const int jB = half ? Nn : 99;
            #pragma unroll 2
            for (int j = jA; j < jB; j++) {
                float4 vv = *(const float4*)(Vs + j * KVS + dl);
                float4 p4 = *(const float4*)(ptw + j * 4);   // broadcast per half
                o0.x += p4.x * vv.x; o0.y += p4.x * vv.y; o0.z += p4.x * vv.z; o0.w += p4.x * vv.w;
                o1.x += p4.y * vv.x; o1.y += p4.y * vv.y; o1.z += p4.y * vv.z; o1.w += p4.y * vv.w;
                o2.x += p4.z * vv.x; o2.y += p4.z * vv.y; o2.z += p4.z * vv.z; o2.w += p4.z * vv.w;
                o3.x += p4.w * vv.x; o3.y += p4.w * vv.y; o3.z += p4.w * vv.z; o3.w += p4.w * vv.w;
            }
            const int t0 = half * 15;
            #pragma unroll
            for (int t = t0; t < t0 + 15; t++) {
                float4 vv = *(const float4*)(rvv_s + t * KVS + dl);
                float4 hh = *(const float4*)(rvh_s + t * KVS + dl);
                float4 a4 = *(const float4*)(svw + t * 4);   // broadcast
                float4 c4 = *(const float4*)(shw + t * 4);
                o0.x += a4.x * vv.x + c4.x * hh.x; o0.y += a4.x * vv.y + c4.x * hh.y;
                o0.z += a4.x * vv.z + c4.x * hh.z; o0.w += a4.x * vv.w + c4.x * hh.w;
                o1.x += a4.y * vv.x + c4.y * hh.x; o1.y += a4.y * vv.y + c4.y * hh.y;
                o1.z += a4.y * vv.z + c4.y * hh.z; o1.w += a4.y * vv.w + c4.y * hh.w;
                o2.x += a4.z * vv.x + c4.z * hh.x; o2.y += a4.z * vv.y + c4.z * hh.y;
                o2.z += a4.z * vv.z + c4.z * hh.z; o2.w += a4.z * vv.w + c4.z * hh.w;
                o3.x += a4.w * vv.x + c4.w * hh.x; o3.y += a4.w * vv.y + c4.w * hh.y;
                o3.z += a4.w * vv.z + c4.w * hh.z; o3.w += a4.w * vv.w + c4.w * hh.w;
            }
        }
        o0.x += __shfl_xor_sync(0xffffffffu, o0.x, 16); o0.y += __shfl_xor_sync(0xffffffffu, o0.y, 16);
        o0.z += __shfl_xor_sync(0xffffffffu, o0.z, 16); o0.w += __shfl_xor_sync(0xffffffffu, o0.w, 16);
        o1.x += __shfl_xor_sync(0xffffffffu, o1.x, 16); o1.y += __shfl_xor_sync(0xffffffffu, o1.y, 16);
        o1.z += __shfl_xor_sync(0xffffffffu, o1.z, 16); o1.w += __shfl_xor_sync(0xffffffffu, o1.w, 16);
        o2.x += __shfl_xor_sync(0xffffffffu, o2.x, 16); o2.y += __shfl_xor_sync(0xffffffffu, o2.y, 16);
        o2.z += __shfl_xor_sync(0xffffffffu, o2.z, 16); o2.w += __shfl_xor_sync(0xffffffffu, o2.w, 16);
        o3.x += __shfl_xor_sync(0xffffffffu, o3.x, 16); o3.y += __shfl_xor_sync(0xffffffffu, o3.y, 16);
        o3.z += __shfl_xor_sync(0xffffffffu, o3.z, 16); o3.w += __shfl_xor_sync(0xffffffffu, o3.w, 16);

        if (lane < 16) {
            const size_t orow0 = ((size_t)(b * Nn + i0)) * Dd + h * HDd + dl;
            *(float4*)(g_o + orow0) = o0;
            if (nq > 1) *(float4*)(g_o + orow0 + Dd) = o1;
            if (nq > 2) *(float4*)(g_o + orow0 + 2 * Dd) = o2;
            if (nq > 3) *(float4*)(g_o + orow0 + 3 * Dd) = o3;
        }
        __syncwarp();
    }
}

// ---------------------------------------------------------------------------
// Launch
// ---------------------------------------------------------------------------
extern "C" void kernel_launch(void* const* d_in, const int* in_sizes, int n_in,
                              void* d_out, int out_size) {
    (void)in_sizes; (void)n_in; (void)out_size;
    const float* x   = (const float*)d_in[0];
    const float* wq  = (const float*)d_in[1];
    const float* bq  = (const float*)d_in[2];
    const float* wk  = (const float*)d_in[3];
    const float* bk  = (const float*)d_in[4];
    const float* wv  = (const float*)d_in[5];
    const float* bv  = (const float*)d_in[6];
    const float* wp  = (const float*)d_in[7];
    const float* bp  = (const float*)d_in[8];
    const float* rkv = (const float*)d_in[9];
    const float* rkh = (const float*)d_in[10];
    const float* rvv = (const float*)d_in[11];
    const float* rvh = (const float*)d_in[12];

    const int nel = MROWS * Dd;
    split_kernel<<<(nel + 255) / 256, 256>>>(x, 0, nel);
    tsplit_kernel<<<dim3(24, 24), dim3(32, 8)>>>(wq, 0);
    tsplit_kernel<<<dim3(24, 24), dim3(32, 8)>>>(wk, 1);
    tsplit_kernel<<<dim3(24, 24), dim3(32, 8)>>>(wv, 2);
    tsplit_kernel<<<dim3(24, 24), dim3(32, 8)>>>(wp, 3);

    cudaFuncSetAttribute(tc_gemm, cudaFuncAttributeMaxDynamicSharedMemorySize, GEMM_SMEM);
    dim3 gg(Dd / 128, (MROWS + 127) / 128);   // (6, 99)
    tc_gemm<<<gg, 256, GEMM_SMEM>>>(bq, nullptr, MROWS, 1, 0, 0);
    tc_gemm<<<gg, 256, GEMM_SMEM>>>(bk, nullptr, MROWS, 2, 1, 0);
    tc_gemm<<<gg, 256, GEMM_SMEM>>>(bv, nullptr, MROWS, 3, 2, 0);

    size_t asmem = (size_t)ATTN_SMEM_FLOATS * sizeof(float);   // 212,960 B
    cudaFuncSetAttribute(attn_kernel, cudaFuncAttributeMaxDynamicSharedMemorySize, (int)asmem);
    attn_kernel<<<Bb * Hh, NTH, asmem>>>(rkv, rkh, rvv, rvh);

    split_kernel<<<(nel + 255) / 256, 256>>>(nullptr, 1, nel);
    tc_gemm<<<gg, 256, GEMM_SMEM>>>(bp, (float*)d_out, MROWS, 0, 3, 1);
}

// round 14
// speedup vs baseline: 1.5315x; 1.5315x over previous
#include <cuda_runtime.h>
#include <cuda_bf16.h>

// Problem constants
#define Bb 64
#define Nn 197
#define Dd 768
#define Hh 12
#define HDd 64
#define MROWS (Bb * Nn)          // 12608
#define NTAB 30
#define SCALE 0.125f

// ---------------------------------------------------------------------------
// Scratch (device globals)
// ---------------------------------------------------------------------------
__device__ float g_q[Bb * Hh * Nn * HDd];
__device__ float g_k[Bb * Hh * Nn * HDd];
__device__ float g_v[Bb * Hh * Nn * HDd];
__device__ float g_o[MROWS * Dd];

__device__ __nv_bfloat16 g_xh[MROWS * Dd];
__device__ __nv_bfloat16 g_xl[MROWS * Dd];
__device__ __nv_bfloat16 g_oh[MROWS * Dd];
__device__ __nv_bfloat16 g_ol[MROWS * Dd];
__device__ __nv_bfloat16 g_wth[4][Dd * Dd];
__device__ __nv_bfloat16 g_wtl[4][Dd * Dd];

// ---------------------------------------------------------------------------
// Warp-level MMA helpers (baseline PTX, sm_80+)
// ---------------------------------------------------------------------------
__device__ __forceinline__ unsigned smem_u32(const void* p) {
    unsigned a;
    asm("{ .reg .u64 t; cvta.to.shared.u64 t, %1; cvt.u32.u64 %0, t; }" : "=r"(a) : "l"(p));
    return a;
}
__device__ __forceinline__ void ldsm4(unsigned* r, unsigned addr) {
    asm volatile("ldmatrix.sync.aligned.m8n8.x4.shared.b16 {%0,%1,%2,%3}, [%4];"
                 : "=r"(r[0]), "=r"(r[1]), "=r"(r[2]), "=r"(r[3]) : "r"(addr));
}
__device__ __forceinline__ void ldsm2(unsigned* r, unsigned addr) {
    asm volatile("ldmatrix.sync.aligned.m8n8.x2.shared.b16 {%0,%1}, [%2];"
                 : "=r"(r[0]), "=r"(r[1]) : "r"(addr));
}
__device__ __forceinline__ void mma16816(float* d, const unsigned* a, const unsigned* b) {
    asm volatile(
        "mma.sync.aligned.m16n8k16.row.col.f32.bf16.bf16.f32 "
        "{%0,%1,%2,%3}, {%4,%5,%6,%7}, {%8,%9}, {%0,%1,%2,%3};"
        : "+f"(d[0]), "+f"(d[1]), "+f"(d[2]), "+f"(d[3])
        : "r"(a[0]), "r"(a[1]), "r"(a[2]), "r"(a[3]), "r"(b[0]), "r"(b[1]));
}

// ---------------------------------------------------------------------------
// Split fp32 -> (hi, lo) bf16
// ---------------------------------------------------------------------------
__global__ __launch_bounds__(256) void split_kernel(const float* __restrict__ src_in,
                                                    int dst_is_o, int n) {
    int i = blockIdx.x * 256 + threadIdx.x;
    if (i >= n) return;
    const float* src = dst_is_o ? g_o : src_in;
    __nv_bfloat16* ph = dst_is_o ? g_oh : g_xh;
    __nv_bfloat16* pl = dst_is_o ? g_ol : g_xl;
    float v = src[i];
    __nv_bfloat16 h = __float2bfloat16(v);
    ph[i] = h;
    pl[i] = __float2bfloat16(v - __bfloat162float(h));
}

// ---------------------------------------------------------------------------
// Transpose + split weights
// ---------------------------------------------------------------------------
__global__ __launch_bounds__(256) void tsplit_kernel(const float* __restrict__ W, int slot) {
    __shared__ float t[32][33];
    int n0 = blockIdx.x * 32, k0 = blockIdx.y * 32;
    int tx = threadIdx.x, ty = threadIdx.y;
    #pragma unroll
    for (int r = 0; r < 4; r++)
        t[ty + 8 * r][tx] = W[(size_t)(k0 + ty + 8 * r) * Dd + n0 + tx];
    __syncthreads();
    __nv_bfloat16* th = g_wth[slot];
    __nv_bfloat16* tl = g_wtl[slot];
    #pragma unroll
    for (int r = 0; r < 4; r++) {
        float v = t[tx][ty + 8 * r];
        __nv_bfloat16 h = __float2bfloat16(v);
        size_t o = (size_t)(n0 + ty + 8 * r) * Dd + k0 + tx;
        th[o] = h;
        tl[o] = __float2bfloat16(v - __bfloat162float(h));
    }
}

// ---------------------------------------------------------------------------
// mma.sync GEMM (unchanged from R12)
// ---------------------------------------------------------------------------
#define KCB 32
#define NCH (Dd / KCB)
#define RSTRIDE 80
#define TILE_SB (128 * RSTRIDE)
#define BUF_SB (4 * TILE_SB)
#define GEMM_SMEM (2 * BUF_SB)

__global__ __launch_bounds__(256) void tc_gemm(const float* __restrict__ bias,
                                               float* __restrict__ out,
                                               int M, int mode, int wslot, int asrc) {
    extern __shared__ char smem[];
    const unsigned sb = smem_u32(smem);
    const int tid = threadIdx.x, warp = tid >> 5, lane = tid & 31;
    const int wm = warp >> 2, wn = warp & 3;
    const int m0 = blockIdx.y * 128, n0 = blockIdx.x * 128;

    const __nv_bfloat16* Ah = asrc ? g_oh : g_xh;
    const __nv_bfloat16* Al = asrc ? g_ol : g_xl;
    const __nv_bfloat16* Bh = g_wth[wslot];
    const __nv_bfloat16* Bl = g_wtl[wslot];

    float acc[4][4][4];
    #pragma unroll
    for (int a = 0; a < 4; a++)
        #pragma unroll
        for (int b = 0; b < 4; b++)
            #pragma unroll
            for (int c = 0; c < 4; c++) acc[a][b][c] = 0.f;

    {
        #pragma unroll
        for (int it = 0; it < 8; it++) {
            int idx = tid + it * 256;
            int tile = idx >> 9, r = (idx >> 2) & 127, g = idx & 3;
            uint4 v = make_uint4(0, 0, 0, 0);
            if (tile == 0)      { if (m0 + r < M) v = ((const uint4*)(Ah + (size_t)(m0 + r) * Dd))[g]; }
            else if (tile == 1) { if (m0 + r < M) v = ((const uint4*)(Al + (size_t)(m0 + r) * Dd))[g]; }
            else if (tile == 2) v = ((const uint4*)(Bh + (size_t)(n0 + r) * Dd))[g];
            else                v = ((const uint4*)(Bl + (size_t)(n0 + r) * Dd))[g];
            *(uint4*)(smem + tile * TILE_SB + r * RSTRIDE + g * 16) = v;
        }
    }
    __syncthreads();

    for (int c = 0; c < NCH; c++) {
        const int cur = c & 1;
        const unsigned bb = sb + cur * BUF_SB;
        const bool more = (c + 1 < NCH);
        uint4 pf[8];
        if (more) {
            const int kc = (c + 1) * KCB;
            #pragma unroll
            for (int it = 0; it < 8; it++) {
                int idx = tid + it * 256;
                int tile = idx >> 9, r = (idx >> 2) & 127, g = idx & 3;
                uint4 v = make_uint4(0, 0, 0, 0);
                if (tile == 0)      { if (m0 + r < M) v = ((const uint4*)(Ah + (size_t)(m0 + r) * Dd + kc))[g]; }
                else if (tile == 1) { if (m0 + r < M) v = ((const uint4*)(Al + (size_t)(m0 + r) * Dd + kc))[g]; }
                else if (tile == 2) v = ((const uint4*)(Bh + (size_t)(n0 + r) * Dd + kc))[g];
                else                v = ((const uint4*)(Bl + (size_t)(n0 + r) * Dd + kc))[g];
                pf[it] = v;
            }
        }

        #pragma unroll
        for (int kb = 0; kb < 2; kb++) {
            unsigned ah[4][4], al[4][4];
            const int arow = (lane & 7) + ((lane >> 3) & 1) * 8;
            const unsigned acb = ((lane >> 4) & 1) * 16 + kb * 32;
            #pragma unroll
            for (int mt = 0; mt < 4; mt++) {
                unsigned aaddr = bb + (unsigned)((wm * 64 + mt * 16 + arow) * RSTRIDE) + acb;
                ldsm4(ah[mt], aaddr);
                ldsm4(al[mt], aaddr + TILE_SB);
            }
            const int nrow = wn * 32 + (lane & 7);
            const unsigned bcb = ((lane >> 3) & 1) * 16 + kb * 32;
            #pragma unroll
            for (int nt = 0; nt < 4; nt++) {
                unsigned baddr = bb + 2 * TILE_SB + (unsigned)((nrow + nt * 8) * RSTRIDE) + bcb;
                unsigned bh[2], bl[2];
                ldsm2(bh, baddr);
                ldsm2(bl, baddr + TILE_SB);
                #pragma unroll
                for (int mt = 0; mt < 4; mt++) {
                    mma16816(acc[mt][nt], ah[mt], bh);
                    mma16816(acc[mt][nt], ah[mt], bl);
                    mma16816(acc[mt][nt], al[mt], bh);
                }
            }
        }

        if (more) {
            char* nbuf = smem + (cur ^ 1) * BUF_SB;
            __syncthreads();
            #pragma unroll
            for (int it = 0; it < 8; it++) {
                int idx = tid + it * 256;
                int tile = idx >> 9, r = (idx >> 2) & 127, g = idx & 3;
                *(uint4*)(nbuf + tile * TILE_SB + r * RSTRIDE + g * 16) = pf[it];
            }
            __syncthreads();
        }
    }

    const int lr = lane >> 2, lc = (lane & 3) * 2;
    #pragma unroll
    for (int mt = 0; mt < 4; mt++) {
        #pragma unroll
        for (int nt = 0; nt < 4; nt++) {
            const int cgl = n0 + wn * 32 + nt * 8 + lc;
            const float b0 = bias[cgl], b1 = bias[cgl + 1];
            #pragma unroll
            for (int hrow = 0; hrow < 2; hrow++) {
                const int r = m0 + wm * 64 + mt * 16 + lr + hrow * 8;
                if (r >= M) continue;
                float2 o2;
                o2.x = acc[mt][nt][hrow * 2 + 0] + b0;
                o2.y = acc[mt][nt][hrow * 2 + 1] + b1;
                if (mode == 0) {
                    *(float2*)(out + (size_t)r * Dd + cgl) = o2;
                } else {
                    float* dst = (mode == 1) ? g_q : (mode == 2) ? g_k : g_v;
                    const int bidx = r / Nn, tok = r % Nn;
                    const int h = cgl >> 6, d = cgl & 63;
                    *(float2*)(dst + (((size_t)bidx * Hh + h) * Nn + tok) * HDd + d) = o2;
                }
            }
        }
    }
}

// ---------------------------------------------------------------------------
// Attention: one CTA per (b,h), 16 warps, groups of 4 queries per warp.
// Scores: SEQUENTIAL per query with q in registers (R12 cost profile),
// probabilities stored transposed pt[j][4].
// V/table phase: ONCE per group — 1 V-row read + 1 p4 broadcast serve 4 queries.
// ---------------------------------------------------------------------------
#define NW 16
#define NTH (32 * NW)             // 512
#define KVS 68
#define NGRP 50                   // ceil(197/4)
#define PTW 788                   // 197*4
#define ATTN_SMEM_FLOATS (2 * Nn * KVS + 4 * NTAB * KVS + NW * 64 + NW * PTW + 4 * NW * 120)

__global__ __launch_bounds__(NTH) void attn_kernel(
    const float* __restrict__ rkv, const float* __restrict__ rkh,
    const float* __restrict__ rvv, const float* __restrict__ rvh)
{
    extern __shared__ float smf[];
    float* Ks    = smf;                       // 197*68
    float* Vs    = Ks + Nn * KVS;             // 197*68
    float* rkv_s = Vs + Nn * KVS;             // 30*68 each
    float* rkh_s = rkv_s + NTAB * KVS;
    float* rvv_s = rkh_s + NTAB * KVS;
    float* rvh_s = rvv_s + NTAB * KVS;
    float* qs    = rvh_s + NTAB * KVS;        // NW*64
    float* pt    = qs + NW * 64;              // NW*788
    float* qv_s  = pt + NW * PTW;             // NW*120 x4
    float* qh_s  = qv_s + NW * 120;
    float* sv_s  = qh_s + NW * 120;
    float* sh_s  = sv_s + NW * 120;

    const int bh   = blockIdx.x;
    const int tid  = threadIdx.x;
    const int warp = tid >> 5, lane = tid & 31;
    const size_t base = (size_t)bh * Nn * HDd;
    const int b = bh / Hh, h = bh % Hh;

    for (int idx = tid; idx < Nn * HDd; idx += NTH) {
        int j = idx >> 6, d = idx & 63;
        Ks[j * KVS + d] = g_k[base + idx];
        Vs[j * KVS + d] = g_v[base + idx];
    }
    for (int idx = tid; idx < NTAB * HDd; idx += NTH) {
        int t = idx >> 6, d = idx & 63;
        rkv_s[t * KVS + d] = rkv[idx];
        rkh_s[t * KVS + d] = rkh[idx];
        rvv_s[t * KVS + d] = rvv[idx];
        rvh_s[t * KVS + d] = rvh[idx];
    }
    __syncthreads();

    float* qw  = qs + warp * 64;
    float* ptw = pt + warp * PTW;
    float* qvw = qv_s + warp * 120;
    float* qhw = qh_s + warp * 120;
    float* svw = sv_s + warp * 120;
    float* shw = sh_s + warp * 120;

    const int half = lane >> 4;
    const int dl   = (lane & 15) * 4;

    for (int grp = warp; grp < NGRP; grp += NW) {
        const int i0 = grp * 4;
        const int nq = (i0 + 4 <= Nn) ? 4 : (Nn - i0);

        if (nq < 4) {   // zero pad columns so V phase sees 0 for unused queries
            for (int u = lane; u < PTW; u += 32) ptw[u] = 0.f;
            __syncwarp();
        }

        int iv[4], ih[4];
        #pragma unroll
        for (int q = 0; q < 4; q++) {
            int i = i0 + q;
            iv[q] = (i == 0) ? 0 : (i - 1) / 14;
            ih[q] = (i == 0) ? 0 : (i - 1) % 14;
        }

        // ----- sequential score phase: q in registers, exactly R12's profile
        for (int q = 0; q < nq; q++) {
            const int i = i0 + q;
            const float* qg = g_q + base + (size_t)i * HDd;
            qw[lane]      = qg[lane];
            qw[lane + 32] = qg[lane + 32];
            __syncwarp();

            float4 qreg[16];
            #pragma unroll
            for (int d4 = 0; d4 < 16; d4++) qreg[d4] = ((const float4*)qw)[d4];

            if (lane < NTAB) {
                float av = 0.f, ah2 = 0.f;
                const float4* tv4 = (const float4*)(rkv_s + lane * KVS);
                const float4* th4 = (const float4*)(rkh_s + lane * KVS);
                #pragma unroll
                for (int d4 = 0; d4 < 16; d4++) {
                    float4 q4 = qreg[d4], v4 = tv4[d4], h4 = th4[d4];
                    av  += q4.x * v4.x + q4.y * v4.y + q4.z * v4.z + q4.w * v4.w;
                    ah2 += q4.x * h4.x + q4.y * h4.y + q4.z * h4.z + q4.w * h4.w;
                }
                qvw[lane * 4 + q] = av;
                qhw[lane * 4 + q] = ah2;
            }
            __syncwarp();

            float s[7];
            float mx = -1e30f;
            #pragma unroll
            for (int jj = 0; jj < 7; jj++) {
                int j = lane + jj * 32;
                if (j < Nn) {
                    const float4* k4 = (const float4*)(Ks + j * KVS);
                    float acc = 0.f;
                    #pragma unroll
                    for (int d4 = 0; d4 < 16; d4++) {
                        float4 q4 = qreg[d4], kk4 = k4[d4];
                        acc += q4.x * kk4.x + q4.y * kk4.y + q4.z * kk4.z + q4.w * kk4.w;
                    }
                    int tv, th;
                    if (i == 0 || j == 0) { tv = 0; th = 0; }
                    else { int rj = j - 1; tv = rj / 14 - iv[q] + 15; th = rj % 14 - ih[q] + 15; }
                    acc += qvw[tv * 4 + q] + qhw[th * 4 + q];
                    s[jj] = acc * SCALE;
                    mx = fmaxf(mx, s[jj]);
                } else s[jj] = -1e30f;
            }
            #pragma unroll
            for (int o = 16; o >= 1; o >>= 1) mx = fmaxf(mx, __shfl_xor_sync(0xffffffffu, mx, o));

            float sum = 0.f;
            #pragma unroll
            for (int jj = 0; jj < 7; jj++) {
                int j = lane + jj * 32;
                if (j < Nn) { s[jj] = __expf(s[jj] - mx); sum += s[jj]; }
                else s[jj] = 0.f;
            }
            #pragma unroll
            for (int o = 16; o >= 1; o >>= 1) sum += __shfl_xor_sync(0xffffffffu, sum, o);
            const float inv = 1.0f / sum;

            #pragma unroll
            for (int jj = 0; jj < 7; jj++) {
                int j = lane + jj * 32;
                if (j < Nn) ptw[j * 4 + q] = s[jj] * inv;
            }
            __syncwarp();
        }

        // ----- bins (transposed [t][4])
        if (lane < NTAB) {
            #pragma unroll
            for (int q = 0; q < 4; q++) {
                float sv = 0.f, sh = 0.f;
                if (q < nq) {
                    if (i0 == 0 && q == 0) {
                        if (lane == 0) { sv = 1.0f; sh = 1.0f; }
                    } else {
                        int g = lane - 15 + iv[q];
                        if (g >= 0 && g < 14) {
                            int j0 = 14 * g + 1;
                            #pragma unroll
                            for (int u = 0; u < 14; u++) sv += ptw[(j0 + u) * 4 + q];
                        }
                        int m = lane - 15 + ih[q];
                        if (m >= 0 && m < 14) {
                            #pragma unroll
                            for (int u = 0; u < 14; u++) sh += ptw[(1 + m + 14 * u) * 4 + q];
                        }
                        if (lane == 0) { sv += ptw[q]; sh += ptw[q]; }
                    }
                }
                svw[lane * 4 + q] = sv;
                shw[lane * 4 + q] = sh;
            }
        }
        __syncwarp();

        // ----- shared V/table phase: one row read serves 4 queries
        float4 o0 = make_float4(0.f, 0.f, 0.f, 0.f);
        float4 o1 = o0, o2 = o0, o3 = o0;
        {
            const int jA = half ? 99 : 0;
            const int jB = half ? Nn : 99;
            #pragma unroll 2
            for (int j = jA; j < jB; j++) {
                float4 vv = *(const float4*)(Vs + j * KVS + dl);
                float4 p4 = *(const float4*)(ptw + j * 4);
                o0.x += p4.x * vv.x; o0.y += p4.x * vv.y; o0.z += p4.x * vv.z; o0.w += p4.x * vv.w;
                o1.x += p4.y * vv.x; o1.y += p4.y * vv.y; o1.z += p4.y * vv.z; o1.w += p4.y * vv.w;
                o2.x += p4.z * vv.x; o2.y += p4.z * vv.y; o2.z += p4.z * vv.z; o2.w += p4.z * vv.w;
                o3.x += p4.w * vv.x; o3.y += p4.w * vv.y; o3.z += p4.w * vv.z; o3.w += p4.w * vv.w;
            }
            const int t0 = half * 15;
            #pragma unroll
            for (int t = t0; t < t0 + 15; t++) {
                float4 vv = *(const float4*)(rvv_s + t * KVS + dl);
                float4 hh = *(const float4*)(rvh_s + t * KVS + dl);
                float4 a4 = *(const float4*)(svw + t * 4);
                float4 c4 = *(const float4*)(shw + t * 4);
                o0.x += a4.x * vv.x + c4.x * hh.x; o0.y += a4.x * vv.y + c4.x * hh.y;
                o0.z += a4.x * vv.z + c4.x * hh.z; o0.w += a4.x * vv.w + c4.x * hh.w;
                o1.x += a4.y * vv.x + c4.y * hh.x; o1.y += a4.y * vv.y + c4.y * hh.y;
                o1.z += a4.y * vv.z + c4.y * hh.z; o1.w += a4.y * vv.w + c4.y * hh.w;
                o2.x += a4.z * vv.x + c4.z * hh.x; o2.y += a4.z * vv.y + c4.z * hh.y;
                o2.z += a4.z * vv.z + c4.z * hh.z; o2.w += a4.z * vv.w + c4.z * hh.w;
                o3.x += a4.w * vv.x + c4.w * hh.x; o3.y += a4.w * vv.y + c4.w * hh.y;
                o3.z += a4.w * vv.z + c4.w * hh.z; o3.w += a4.w * vv.w + c4.w * hh.w;
            }
        }
        o0.x += __shfl_xor_sync(0xffffffffu, o0.x, 16); o0.y += __shfl_xor_sync(0xffffffffu, o0.y, 16);
        o0.z += __shfl_xor_sync(0xffffffffu, o0.z, 16); o0.w += __shfl_xor_sync(0xffffffffu, o0.w, 16);
        o1.x += __shfl_xor_sync(0xffffffffu, o1.x, 16); o1.y += __shfl_xor_sync(0xffffffffu, o1.y, 16);
        o1.z += __shfl_xor_sync(0xffffffffu, o1.z, 16); o1.w += __shfl_xor_sync(0xffffffffu, o1.w, 16);
        o2.x += __shfl_xor_sync(0xffffffffu, o2.x, 16); o2.y += __shfl_xor_sync(0xffffffffu, o2.y, 16);
        o2.z += __shfl_xor_sync(0xffffffffu, o2.z, 16); o2.w += __shfl_xor_sync(0xffffffffu, o2.w, 16);
        o3.x += __shfl_xor_sync(0xffffffffu, o3.x, 16); o3.y += __shfl_xor_sync(0xffffffffu, o3.y, 16);
        o3.z += __shfl_xor_sync(0xffffffffu, o3.z, 16); o3.w += __shfl_xor_sync(0xffffffffu, o3.w, 16);

        if (lane < 16) {
            const size_t orow0 = ((size_t)(b * Nn + i0)) * Dd + h * HDd + dl;
            *(float4*)(g_o + orow0) = o0;
            if (nq > 1) *(float4*)(g_o + orow0 + Dd) = o1;
            if (nq > 2) *(float4*)(g_o + orow0 + 2 * Dd) = o2;
            if (nq > 3) *(float4*)(g_o + orow0 + 3 * Dd) = o3;
        }
        __syncwarp();
    }
}

// ---------------------------------------------------------------------------
// Launch
// ---------------------------------------------------------------------------
extern "C" void kernel_launch(void* const* d_in, const int* in_sizes, int n_in,
                              void* d_out, int out_size) {
    (void)in_sizes; (void)n_in; (void)out_size;
    const float* x   = (const float*)d_in[0];
    const float* wq  = (const float*)d_in[1];
    const float* bq  = (const float*)d_in[2];
    const float* wk  = (const float*)d_in[3];
    const float* bk  = (const float*)d_in[4];
    const float* wv  = (const float*)d_in[5];
    const float* bv  = (const float*)d_in[6];
    const float* wp  = (const float*)d_in[7];
    const float* bp  = (const float*)d_in[8];
    const float* rkv = (const float*)d_in[9];
    const float* rkh = (const float*)d_in[10];
    const float* rvv = (const float*)d_in[11];
    const float* rvh = (const float*)d_in[12];

    const int nel = MROWS * Dd;
    split_kernel<<<(nel + 255) / 256, 256>>>(x, 0, nel);
    tsplit_kernel<<<dim3(24, 24), dim3(32, 8)>>>(wq, 0);
    tsplit_kernel<<<dim3(24, 24), dim3(32, 8)>>>(wk, 1);
    tsplit_kernel<<<dim3(24, 24), dim3(32, 8)>>>(wv, 2);
    tsplit_kernel<<<dim3(24, 24), dim3(32, 8)>>>(wp, 3);

    cudaFuncSetAttribute(tc_gemm, cudaFuncAttributeMaxDynamicSharedMemorySize, GEMM_SMEM);
    dim3 gg(Dd / 128, (MROWS + 127) / 128);   // (6, 99)
    tc_gemm<<<gg, 256, GEMM_SMEM>>>(bq, nullptr, MROWS, 1, 0, 0);
    tc_gemm<<<gg, 256, GEMM_SMEM>>>(bk, nullptr, MROWS, 2, 1, 0);
    tc_gemm<<<gg, 256, GEMM_SMEM>>>(bv, nullptr, MROWS, 3, 2, 0);

    size_t asmem = (size_t)ATTN_SMEM_FLOATS * sizeof(float);   // 225,056 B
    cudaFuncSetAttribute(attn_kernel, cudaFuncAttributeMaxDynamicSharedMemorySize, (int)asmem);
    attn_kernel<<<Bb * Hh, NTH, asmem>>>(rkv, rkh, rvv, rvh);

    split_kernel<<<(nel + 255) / 256, 256>>>(nullptr, 1, nel);
    tc_gemm<<<gg, 256, GEMM_SMEM>>>(bp, (float*)d_out, MROWS, 0, 3, 1);
}

// round 15
// speedup vs baseline: 1.6983x; 1.1089x over previous
#include <cuda_runtime.h>
#include <cuda_bf16.h>

// Problem constants
#define Bb 64
#define Nn 197
#define Dd 768
#define Hh 12
#define HDd 64
#define MROWS (Bb * Nn)          // 12608
#define NTAB 30
#define SCALE 0.125f

// ---------------------------------------------------------------------------
// Scratch (device globals)
// ---------------------------------------------------------------------------
__device__ float g_q[Bb * Hh * Nn * HDd];
__device__ float g_k[Bb * Hh * Nn * HDd];
__device__ float g_v[Bb * Hh * Nn * HDd];
__device__ float g_o[MROWS * Dd];

__device__ __nv_bfloat16 g_xh[MROWS * Dd];
__device__ __nv_bfloat16 g_xl[MROWS * Dd];
__device__ __nv_bfloat16 g_oh[MROWS * Dd];
__device__ __nv_bfloat16 g_ol[MROWS * Dd];
__device__ __nv_bfloat16 g_wth[4][Dd * Dd];
__device__ __nv_bfloat16 g_wtl[4][Dd * Dd];

// ---------------------------------------------------------------------------
// Warp-level MMA helpers (baseline PTX, sm_80+)
// ---------------------------------------------------------------------------
__device__ __forceinline__ unsigned smem_u32(const void* p) {
    unsigned a;
    asm("{ .reg .u64 t; cvta.to.shared.u64 t, %1; cvt.u32.u64 %0, t; }" : "=r"(a) : "l"(p));
    return a;
}
__device__ __forceinline__ void ldsm4(unsigned* r, unsigned addr) {
    asm volatile("ldmatrix.sync.aligned.m8n8.x4.shared.b16 {%0,%1,%2,%3}, [%4];"
                 : "=r"(r[0]), "=r"(r[1]), "=r"(r[2]), "=r"(r[3]) : "r"(addr));
}
__device__ __forceinline__ void ldsm2(unsigned* r, unsigned addr) {
    asm volatile("ldmatrix.sync.aligned.m8n8.x2.shared.b16 {%0,%1}, [%2];"
                 : "=r"(r[0]), "=r"(r[1]) : "r"(addr));
}
__device__ __forceinline__ void mma16816(float* d, const unsigned* a, const unsigned* b) {
    asm volatile(
        "mma.sync.aligned.m16n8k16.row.col.f32.bf16.bf16.f32 "
        "{%0,%1,%2,%3}, {%4,%5,%6,%7}, {%8,%9}, {%0,%1,%2,%3};"
        : "+f"(d[0]), "+f"(d[1]), "+f"(d[2]), "+f"(d[3])
        : "r"(a[0]), "r"(a[1]), "r"(a[2]), "r"(a[3]), "r"(b[0]), "r"(b[1]));
}

// ---------------------------------------------------------------------------
// Split fp32 -> (hi, lo) bf16
// ---------------------------------------------------------------------------
__global__ __launch_bounds__(256) void split_kernel(const float* __restrict__ src_in,
                                                    int dst_is_o, int n) {
    int i = blockIdx.x * 256 + threadIdx.x;
    if (i >= n) return;
    const float* src = dst_is_o ? g_o : src_in;
    __nv_bfloat16* ph = dst_is_o ? g_oh : g_xh;
    __nv_bfloat16* pl = dst_is_o ? g_ol : g_xl;
    float v = src[i];
    __nv_bfloat16 h = __float2bfloat16(v);
    ph[i] = h;
    pl[i] = __float2bfloat16(v - __bfloat162float(h));
}

// ---------------------------------------------------------------------------
// Transpose + split weights
// ---------------------------------------------------------------------------
__global__ __launch_bounds__(256) void tsplit_kernel(const float* __restrict__ W, int slot) {
    __shared__ float t[32][33];
    int n0 = blockIdx.x * 32, k0 = blockIdx.y * 32;
    int tx = threadIdx.x, ty = threadIdx.y;
    #pragma unroll
    for (int r = 0; r < 4; r++)
        t[ty + 8 * r][tx] = W[(size_t)(k0 + ty + 8 * r) * Dd + n0 + tx];
    __syncthreads();
    __nv_bfloat16* th = g_wth[slot];
    __nv_bfloat16* tl = g_wtl[slot];
    #pragma unroll
    for (int r = 0; r < 4; r++) {
        float v = t[tx][ty + 8 * r];
        __nv_bfloat16 h = __float2bfloat16(v);
        size_t o = (size_t)(n0 + ty + 8 * r) * Dd + k0 + tx;
        th[o] = h;
        tl[o] = __float2bfloat16(v - __bfloat162float(h));
    }
}

// ---------------------------------------------------------------------------
// mma.sync GEMM (unchanged from R12)
// ---------------------------------------------------------------------------
#define KCB 32
#define NCH (Dd / KCB)
#define RSTRIDE 80
#define TILE_SB (128 * RSTRIDE)
#define BUF_SB (4 * TILE_SB)
#define GEMM_SMEM (2 * BUF_SB)

__global__ __launch_bounds__(256) void tc_gemm(const float* __restrict__ bias,
                                               float* __restrict__ out,
                                               int M, int mode, int wslot, int asrc) {
    extern __shared__ char smem[];
    const unsigned sb = smem_u32(smem);
    const int tid = threadIdx.x, warp = tid >> 5, lane = tid & 31;
    const int wm = warp >> 2, wn = warp & 3;
    const int m0 = blockIdx.y * 128, n0 = blockIdx.x * 128;

    const __nv_bfloat16* Ah = asrc ? g_oh : g_xh;
    const __nv_bfloat16* Al = asrc ? g_ol : g_xl;
    const __nv_bfloat16* Bh = g_wth[wslot];
    const __nv_bfloat16* Bl = g_wtl[wslot];

    float acc[4][4][4];
    #pragma unroll
    for (int a = 0; a < 4; a++)
        #pragma unroll
        for (int b = 0; b < 4; b++)
            #pragma unroll
            for (int c = 0; c < 4; c++) acc[a][b][c] = 0.f;

    {
        #pragma unroll
        for (int it = 0; it < 8; it++) {
            int idx = tid + it * 256;
            int tile = idx >> 9, r = (idx >> 2) & 127, g = idx & 3;
            uint4 v = make_uint4(0, 0, 0, 0);
            if (tile == 0)      { if (m0 + r < M) v = ((const uint4*)(Ah + (size_t)(m0 + r) * Dd))[g]; }
            else if (tile == 1) { if (m0 + r < M) v = ((const uint4*)(Al + (size_t)(m0 + r) * Dd))[g]; }
            else if (tile == 2) v = ((const uint4*)(Bh + (size_t)(n0 + r) * Dd))[g];
            else                v = ((const uint4*)(Bl + (size_t)(n0 + r) * Dd))[g];
            *(uint4*)(smem + tile * TILE_SB + r * RSTRIDE + g * 16) = v;
        }
    }
    __syncthreads();

    for (int c = 0; c < NCH; c++) {
        const int cur = c & 1;
        const unsigned bb = sb + cur * BUF_SB;
        const bool more = (c + 1 < NCH);
        uint4 pf[8];
        if (more) {
            const int kc = (c + 1) * KCB;
            #pragma unroll
            for (int it = 0; it < 8; it++) {
                int idx = tid + it * 256;
                int tile = idx >> 9, r = (idx >> 2) & 127, g = idx & 3;
                uint4 v = make_uint4(0, 0, 0, 0);
                if (tile == 0)      { if (m0 + r < M) v = ((const uint4*)(Ah + (size_t)(m0 + r) * Dd + kc))[g]; }
                else if (tile == 1) { if (m0 + r < M) v = ((const uint4*)(Al + (size_t)(m0 + r) * Dd + kc))[g]; }
                else if (tile == 2) v = ((const uint4*)(Bh + (size_t)(n0 + r) * Dd + kc))[g];
                else                v = ((const uint4*)(Bl + (size_t)(n0 + r) * Dd + kc))[g];
                pf[it] = v;
            }
        }

        #pragma unroll
        for (int kb = 0; kb < 2; kb++) {
            unsigned ah[4][4], al[4][4];
            const int arow = (lane & 7) + ((lane >> 3) & 1) * 8;
            const unsigned acb = ((lane >> 4) & 1) * 16 + kb * 32;
            #pragma unroll
            for (int mt = 0; mt < 4; mt++) {
                unsigned aaddr = bb + (unsigned)((wm * 64 + mt * 16 + arow) * RSTRIDE) + acb;
                ldsm4(ah[mt], aaddr);
                ldsm4(al[mt], aaddr + TILE_SB);
            }
            const int nrow = wn * 32 + (lane & 7);
            const unsigned bcb = ((lane >> 3) & 1) * 16 + kb * 32;
            #pragma unroll
            for (int nt = 0; nt < 4; nt++) {
                unsigned baddr = bb + 2 * TILE_SB + (unsigned)((nrow + nt * 8) * RSTRIDE) + bcb;
                unsigned bh[2], bl[2];
                ldsm2(bh, baddr);
                ldsm2(bl, baddr + TILE_SB);
                #pragma unroll
                for (int mt = 0; mt < 4; mt++) {
                    mma16816(acc[mt][nt], ah[mt], bh);
                    mma16816(acc[mt][nt], ah[mt], bl);
                    mma16816(acc[mt][nt], al[mt], bh);
                }
            }
        }

        if (more) {
            char* nbuf = smem + (cur ^ 1) * BUF_SB;
            __syncthreads();
            #pragma unroll
            for (int it = 0; it < 8; it++) {
                int idx = tid + it * 256;
                int tile = idx >> 9, r = (idx >> 2) & 127, g = idx & 3;
                *(uint4*)(nbuf + tile * TILE_SB + r * RSTRIDE + g * 16) = pf[it];
            }
            __syncthreads();
        }
    }

    const int lr = lane >> 2, lc = (lane & 3) * 2;
    #pragma unroll
    for (int mt = 0; mt < 4; mt++) {
        #pragma unroll
        for (int nt = 0; nt < 4; nt++) {
            const int cgl = n0 + wn * 32 + nt * 8 + lc;
            const float b0 = bias[cgl], b1 = bias[cgl + 1];
            #pragma unroll
            for (int hrow = 0; hrow < 2; hrow++) {
                const int r = m0 + wm * 64 + mt * 16 + lr + hrow * 8;
                if (r >= M) continue;
                float2 o2;
                o2.x = acc[mt][nt][hrow * 2 + 0] + b0;
                o2.y = acc[mt][nt][hrow * 2 + 1] + b1;
                if (mode == 0) {
                    *(float2*)(out + (size_t)r * Dd + cgl) = o2;
                } else {
                    float* dst = (mode == 1) ? g_q : (mode == 2) ? g_k : g_v;
                    const int bidx = r / Nn, tok = r % Nn;
                    const int h = cgl >> 6, d = cgl & 63;
                    *(float2*)(dst + (((size_t)bidx * Hh + h) * Nn + tok) * HDd + d) = o2;
                }
            }
        }
    }
}

// ---------------------------------------------------------------------------
// Attention: one CTA per (b,h), 12 warps, 4 queries/group.
// Score phase: 2 query-PAIRS, d-split across half-warps — each half holds
// 32 floats of q per query (2 queries fit in 64 regs), K rows read ONCE per
// pair (both halves read complementary d-halves), combine via shfl_xor(16).
// Bins + shared V/table phase identical to R14.
// ---------------------------------------------------------------------------
#define NW 12
#define NTH (32 * NW)             // 384
#define KVS 68
#define NGRP 50                   // ceil(197/4)
#define PTW 788                   // 197*4
#define NJT 13                    // j tiles of 16 rows (13*16 = 208 >= 197)
#define ATTN_SMEM_FLOATS (2 * Nn * KVS + 4 * NTAB * KVS + NW * 128 + NW * PTW + 4 * NW * 120)

__global__ __launch_bounds__(NTH) void attn_kernel(
    const float* __restrict__ rkv, const float* __restrict__ rkh,
    const float* __restrict__ rvv, const float* __restrict__ rvh)
{
    extern __shared__ float smf[];
    float* Ks    = smf;                       // 197*68
    float* Vs    = Ks + Nn * KVS;             // 197*68
    float* rkv_s = Vs + Nn * KVS;             // 30*68 each
    float* rkh_s = rkv_s + NTAB * KVS;
    float* rvv_s = rkh_s + NTAB * KVS;
    float* rvh_s = rvv_s + NTAB * KVS;
    float* qs    = rvh_s + NTAB * KVS;        // NW*128 (2 staged queries)
    float* pt    = qs + NW * 128;             // NW*788
    float* qv_s  = pt + NW * PTW;             // NW*120 x4
    float* qh_s  = qv_s + NW * 120;
    float* sv_s  = qh_s + NW * 120;
    float* sh_s  = sv_s + NW * 120;

    const int bh   = blockIdx.x;
    const int tid  = threadIdx.x;
    const int warp = tid >> 5, lane = tid & 31;
    const size_t base = (size_t)bh * Nn * HDd;
    const int b = bh / Hh, h = bh % Hh;

    for (int idx = tid; idx < Nn * HDd; idx += NTH) {
        int j = idx >> 6, d = idx & 63;
        Ks[j * KVS + d] = g_k[base + idx];
        Vs[j * KVS + d] = g_v[base + idx];
    }
    for (int idx = tid; idx < NTAB * HDd; idx += NTH) {
        int t = idx >> 6, d = idx & 63;
        rkv_s[t * KVS + d] = rkv[idx];
        rkh_s[t * KVS + d] = rkh[idx];
        rvv_s[t * KVS + d] = rvv[idx];
        rvh_s[t * KVS + d] = rvh[idx];
    }
    __syncthreads();

    float* qw  = qs + warp * 128;
    float* ptw = pt + warp * PTW;
    float* qvw = qv_s + warp * 120;
    float* qhw = qh_s + warp * 120;
    float* svw = sv_s + warp * 120;
    float* shw = sh_s + warp * 120;

    const int half = lane >> 4;        // d-half owner (score) / j-half (V phase)
    const int l16  = lane & 15;
    const int dh   = half * 32;        // d offset for score phase
    const int dl   = l16 * 4;          // d offset for V phase

    for (int grp = warp; grp < NGRP; grp += NW) {
        const int i0 = grp * 4;
        const int nq = (i0 + 4 <= Nn) ? 4 : (Nn - i0);

        if (nq < 4) {   // zero pad columns so V phase sees 0 for unused queries
            for (int u = lane; u < PTW; u += 32) ptw[u] = 0.f;
            __syncwarp();
        }

        int iv[4], ih[4];
        #pragma unroll
        for (int q = 0; q < 4; q++) {
            int i = i0 + q;
            iv[q] = (i == 0) ? 0 : (i - 1) / 14;
            ih[q] = (i == 0) ? 0 : (i - 1) % 14;
        }

        // ===== score phase: 2 pairs, d-split halves =====
        #pragma unroll
        for (int p = 0; p < 2; p++) {
            const int qa = 2 * p, qb = 2 * p + 1;
            const bool va = (qa < nq), vb = (qb < nq);
            const int ia = i0 + qa, ib = i0 + qb;

            // stage both q rows (zeros when invalid)
            {
                const float* qgA = g_q + base + (size_t)ia * HDd;
                const float* qgB = g_q + base + (size_t)ib * HDd;
                qw[lane]      = va ? qgA[lane] : 0.f;
                qw[32 + lane] = va ? qgA[32 + lane] : 0.f;
                qw[64 + lane] = vb ? qgB[lane] : 0.f;
                qw[96 + lane] = vb ? qgB[32 + lane] : 0.f;
            }
            __syncwarp();

            // half-split q registers: 8 float4 per query (32 floats)
            float4 qA[8], qB[8];
            #pragma unroll
            for (int t = 0; t < 8; t++) {
                qA[t] = *(const float4*)(qw + dh + 4 * t);
                qB[t] = *(const float4*)(qw + 64 + dh + 4 * t);
            }

            // table projections (half-split, 2 passes over t)
            #pragma unroll
            for (int pass = 0; pass < 2; pass++) {
                const int t = l16 + pass * 16;   // 0..31; t>=NTAB lanes compute garbage, not stored
                const float4* tv4 = (const float4*)(rkv_s + t * KVS + dh);
                const float4* th4 = (const float4*)(rkh_s + t * KVS + dh);
                float avA = 0.f, ahA = 0.f, avB = 0.f, ahB = 0.f;
                #pragma unroll
                for (int u = 0; u < 8; u++) {
                    float4 tv = tv4[u], th = th4[u];
                    avA += qA[u].x * tv.x + qA[u].y * tv.y + qA[u].z * tv.z + qA[u].w * tv.w;
                    ahA += qA[u].x * th.x + qA[u].y * th.y + qA[u].z * th.z + qA[u].w * th.w;
                    avB += qB[u].x * tv.x + qB[u].y * tv.y + qB[u].z * tv.z + qB[u].w * tv.w;
                    ahB += qB[u].x * th.x + qB[u].y * th.y + qB[u].z * th.z + qB[u].w * th.w;
                }
                avA += __shfl_xor_sync(0xffffffffu, avA, 16);
                ahA += __shfl_xor_sync(0xffffffffu, ahA, 16);
                avB += __shfl_xor_sync(0xffffffffu, avB, 16);
                ahB += __shfl_xor_sync(0xffffffffu, ahB, 16);
                if (t < NTAB) {
                    if (half == 0) { qvw[t * 4 + qa] = avA; qhw[t * 4 + qa] = ahA; }
                    else           { qvw[t * 4 + qb] = avB; qhw[t * 4 + qb] = ahB; }
                }
            }
            __syncwarp();

            // K pass: one read of K serves both queries
            float sA[NJT], sB[NJT];
            #pragma unroll
            for (int jj = 0; jj < NJT; jj++) {
                const int j = jj * 16 + l16;
                float aA = 0.f, aB = 0.f;
                if (j < Nn) {
                    const float4* k4 = (const float4*)(Ks + j * KVS + dh);
                    #pragma unroll
                    for (int u = 0; u < 8; u++) {
                        float4 kk = k4[u];
                        aA += qA[u].x * kk.x + qA[u].y * kk.y + qA[u].z * kk.z + qA[u].w * kk.w;
                        aB += qB[u].x * kk.x + qB[u].y * kk.y + qB[u].z * kk.z + qB[u].w * kk.w;
                    }
                }
                sA[jj] = aA;
                sB[jj] = aB;
            }
            #pragma unroll
            for (int jj = 0; jj < NJT; jj++) {
                sA[jj] += __shfl_xor_sync(0xffffffffu, sA[jj], 16);
                sB[jj] += __shfl_xor_sync(0xffffffffu, sB[jj], 16);
            }

            // bias + scale + mask
            #pragma unroll
            for (int jj = 0; jj < NJT; jj++) {
                const int j = jj * 16 + l16;
                if (j < Nn) {
                    const int rjd = (j == 0) ? 0 : (j - 1) / 14;
                    const int rjm = (j == 0) ? 0 : (j - 1) % 14;
                    int tvA, thA, tvB, thB;
                    if (j == 0 || ia == 0) { tvA = 0; thA = 0; }
                    else { tvA = rjd - iv[qa] + 15; thA = rjm - ih[qa] + 15; }
                    if (j == 0 || ib == 0) { tvB = 0; thB = 0; }
                    else { tvB = rjd - iv[qb] + 15; thB = rjm - ih[qb] + 15; }
                    sA[jj] = (sA[jj] + qvw[tvA * 4 + qa] + qhw[thA * 4 + qa]) * SCALE;
                    sB[jj] = (sB[jj] + qvw[tvB * 4 + qb] + qhw[thB * 4 + qb]) * SCALE;
                } else {
                    sA[jj] = -1e30f;
                    sB[jj] = -1e30f;
                }
            }

            // softmax (reduce over 16-lane groups; halves hold identical rows)
            float mxA = -1e30f, mxB = -1e30f;
            #pragma unroll
            for (int jj = 0; jj < NJT; jj++) { mxA = fmaxf(mxA, sA[jj]); mxB = fmaxf(mxB, sB[jj]); }
            #pragma unroll
            for (int o = 8; o >= 1; o >>= 1) {
                mxA = fmaxf(mxA, __shfl_xor_sync(0xffffffffu, mxA, o));
                mxB = fmaxf(mxB, __shfl_xor_sync(0xffffffffu, mxB, o));
            }
            float smA = 0.f, smB = 0.f;
            #pragma unroll
            for (int jj = 0; jj < NJT; jj++) {
                sA[jj] = __expf(sA[jj] - mxA); smA += sA[jj];
                sB[jj] = __expf(sB[jj] - mxB); smB += sB[jj];
            }
            #pragma unroll
            for (int o = 8; o >= 1; o >>= 1) {
                smA += __shfl_xor_sync(0xffffffffu, smA, o);
                smB += __shfl_xor_sync(0xffffffffu, smB, o);
            }
            const float invA = 1.0f / smA, invB = 1.0f / smB;

            // half 0 stores query A, half 1 stores query B
            if (half == 0) {
                if (va) {
                    #pragma unroll
                    for (int jj = 0; jj < NJT; jj++) {
                        const int j = jj * 16 + l16;
                        if (j < Nn) ptw[j * 4 + qa] = sA[jj] * invA;
                    }
                }
            } else {
                if (vb) {
                    #pragma unroll
                    for (int jj = 0; jj < NJT; jj++) {
                        const int j = jj * 16 + l16;
                        if (j < Nn) ptw[j * 4 + qb] = sB[jj] * invB;
                    }
                }
            }
            __syncwarp();
        }

        // ===== bins (transposed [t][4]) =====
        if (lane < NTAB) {
            #pragma unroll
            for (int q = 0; q < 4; q++) {
                float sv = 0.f, sh = 0.f;
                if (q < nq) {
                    if (i0 == 0 && q == 0) {
                        if (lane == 0) { sv = 1.0f; sh = 1.0f; }
                    } else {
                        int g = lane - 15 + iv[q];
                        if (g >= 0 && g < 14) {
                            int j0 = 14 * g + 1;
                            #pragma unroll
                            for (int u = 0; u < 14; u++) sv += ptw[(j0 + u) * 4 + q];
                        }
                        int m = lane - 15 + ih[q];
                        if (m >= 0 && m < 14) {
                            #pragma unroll
                            for (int u = 0; u < 14; u++) sh += ptw[(1 + m + 14 * u) * 4 + q];
                        }
                        if (lane == 0) { sv += ptw[q]; sh += ptw[q]; }
                    }
                }
                svw[lane * 4 + q] = sv;
                shw[lane * 4 + q] = sh;
            }
        }
        __syncwarp();

        // ===== shared V/table phase: one row read serves 4 queries =====
        float4 o0 = make_float4(0.f, 0.f, 0.f, 0.f);
        float4 o1 = o0, o2 = o0, o3 = o0;
        {
            const int jA = half ? 99 : 0;
            const int jB = half ? Nn : 99;
            #pragma unroll 2
            for (int j = jA; j < jB; j++) {
                float4 vv = *(const float4*)(Vs + j * KVS + dl);
                float4 p4 = *(const float4*)(ptw + j * 4);
                o0.x += p4.x * vv.x; o0.y += p4.x * vv.y; o0.z += p4.x * vv.z; o0.w += p4.x * vv.w;
                o1.x += p4.y * vv.x; o1.y += p4.y * vv.y; o1.z += p4.y * vv.z; o1.w += p4.y * vv.w;
                o2.x += p4.z * vv.x; o2.y += p4.z * vv.y; o2.z += p4.z * vv.z; o2.w += p4.z * vv.w;
                o3.x += p4.w * vv.x; o3.y += p4.w * vv.y; o3.z += p4.w * vv.z; o3.w += p4.w * vv.w;
            }
            const int t0 = half * 15;
            #pragma unroll
            for (int t = t0; t < t0 + 15; t++) {
                float4 vv = *(const float4*)(rvv_s + t * KVS + dl);
                float4 hh = *(const float4*)(rvh_s + t * KVS + dl);
                float4 a4 = *(const float4*)(svw + t * 4);
                float4 c4 = *(const float4*)(shw + t * 4);
                o0.x += a4.x * vv.x + c4.x * hh.x; o0.y += a4.x * vv.y + c4.x * hh.y;
                o0.z += a4.x * vv.z + c4.x * hh.z; o0.w += a4.x * vv.w + c4.x * hh.w;
                o1.x += a4.y * vv.x + c4.y * hh.x; o1.y += a4.y * vv.y + c4.y * hh.y;
                o1.z += a4.y * vv.z + c4.y * hh.z; o1.w += a4.y * vv.w + c4.y * hh.w;
                o2.x += a4.z * vv.x + c4.z * hh.x; o2.y += a4.z * vv.y + c4.z * hh.y;
                o2.z += a4.z * vv.z + c4.z * hh.z; o2.w += a4.z * vv.w + c4.z * hh.w;
                o3.x += a4.w * vv.x + c4.w * hh.x; o3.y += a4.w * vv.y + c4.w * hh.y;
                o3.z += a4.w * vv.z + c4.w * hh.z; o3.w += a4.w * vv.w + c4.w * hh.w;
            }
        }
        o0.x += __shfl_xor_sync(0xffffffffu, o0.x, 16); o0.y += __shfl_xor_sync(0xffffffffu, o0.y, 16);
        o0.z += __shfl_xor_sync(0xffffffffu, o0.z, 16); o0.w += __shfl_xor_sync(0xffffffffu, o0.w, 16);
        o1.x += __shfl_xor_sync(0xffffffffu, o1.x, 16); o1.y += __shfl_xor_sync(0xffffffffu, o1.y, 16);
        o1.z += __shfl_xor_sync(0xffffffffu, o1.z, 16); o1.w += __shfl_xor_sync(0xffffffffu, o1.w, 16);
        o2.x += __shfl_xor_sync(0xffffffffu, o2.x, 16); o2.y += __shfl_xor_sync(0xffffffffu, o2.y, 16);
        o2.z += __shfl_xor_sync(0xffffffffu, o2.z, 16); o2.w += __shfl_xor_sync(0xffffffffu, o2.w, 16);
        o3.x += __shfl_xor_sync(0xffffffffu, o3.x, 16); o3.y += __shfl_xor_sync(0xffffffffu, o3.y, 16);
        o3.z += __shfl_xor_sync(0xffffffffu, o3.z, 16); o3.w += __shfl_xor_sync(0xffffffffu, o3.w, 16);

        if (lane < 16) {
            const size_t orow0 = ((size_t)(b * Nn + i0)) * Dd + h * HDd + dl;
            *(float4*)(g_o + orow0) = o0;
            if (nq > 1) *(float4*)(g_o + orow0 + Dd) = o1;
            if (nq > 2) *(float4*)(g_o + orow0 + 2 * Dd) = o2;
            if (nq > 3) *(float4*)(g_o + orow0 + 3 * Dd) = o3;
        }
        __syncwarp();
    }
}

// ---------------------------------------------------------------------------
// Launch
// ---------------------------------------------------------------------------
extern "C" void kernel_launch(void* const* d_in, const int* in_sizes, int n_in,
                              void* d_out, int out_size) {
    (void)in_sizes; (void)n_in; (void)out_size;
    const float* x   = (const float*)d_in[0];
    const float* wq  = (const float*)d_in[1];
    const float* bq  = (const float*)d_in[2];
    const float* wk  = (const float*)d_in[3];
    const float* bk  = (const float*)d_in[4];
    const float* wv  = (const float*)d_in[5];
    const float* bv  = (const float*)d_in[6];
    const float* wp  = (const float*)d_in[7];
    const float* bp  = (const float*)d_in[8];
    const float* rkv = (const float*)d_in[9];
    const float* rkh = (const float*)d_in[10];
    const float* rvv = (const float*)d_in[11];
    const float* rvh = (const float*)d_in[12];

    const int nel = MROWS * Dd;
    split_kernel<<<(nel + 255) / 256, 256>>>(x, 0, nel);
    tsplit_kernel<<<dim3(24, 24), dim3(32, 8)>>>(wq, 0);
    tsplit_kernel<<<dim3(24, 24), dim3(32, 8)>>>(wk, 1);
    tsplit_kernel<<<dim3(24, 24), dim3(32, 8)>>>(wv, 2);
    tsplit_kernel<<<dim3(24, 24), dim3(32, 8)>>>(wp, 3);

    cudaFuncSetAttribute(tc_gemm, cudaFuncAttributeMaxDynamicSharedMemorySize, GEMM_SMEM);
    dim3 gg(Dd / 128, (MROWS + 127) / 128);   // (6, 99)
    tc_gemm<<<gg, 256, GEMM_SMEM>>>(bq, nullptr, MROWS, 1, 0, 0);
    tc_gemm<<<gg, 256, GEMM_SMEM>>>(bk, nullptr, MROWS, 2, 1, 0);
    tc_gemm<<<gg, 256, GEMM_SMEM>>>(bv, nullptr, MROWS, 3, 2, 0);

    size_t asmem = (size_t)ATTN_SMEM_FLOATS * sizeof(float);   // ~207 KB
    cudaFuncSetAttribute(attn_kernel, cudaFuncAttributeMaxDynamicSharedMemorySize, (int)asmem);
    attn_kernel<<<Bb * Hh, NTH, asmem>>>(rkv, rkh, rvv, rvh);

    split_kernel<<<(nel + 255) / 256, 256>>>(nullptr, 1, nel);
    tc_gemm<<<gg, 256, GEMM_SMEM>>>(bp, (float*)d_out, MROWS, 0, 3, 1);
}